// round 4
// baseline (speedup 1.0000x reference)
#include <cuda_runtime.h>
#include <cuda_bf16.h>
#include <cstdint>

// ---------------------------------------------------------------------------
// BarrierNet on GB300, round 4:
//   512-thread CTA (16 warps, 4x4 warp grid, 32x32 tile/warp), 128 rows/CTA.
//   Double-buffered cp.async weight staging (loads hidden behind MMA).
//   bf16 m16n8k16 mma.sync + tanh.approx.bf16x2 epilogue.
// ---------------------------------------------------------------------------

#define THREADS 512
#define ROWS_PER_CTA 128
#define STRB 136            // bf16 elems per smem row -> bank permutation
#define ROWB (STRB * 2)     // 272 bytes per row
#define WBUF_BYTES 35328    // 128*272 weight rows + 512B fp32 bias

// byte offsets into dynamic smem
#define OFF_W0   0
#define OFF_W1B  35328
#define OFF_H    70656
#define OFF_A    105472
#define OFF_X    140288                 // 128*6 f32
#define OFF_FC1W 143360                 // 768 f32
#define OFF_FC1B 146432                 // 128 f32
#define OFF_W31  146944                 // 384 f32
#define OFF_W32  148480                 // 256 f32
#define OFF_SML  149504                 // 17 f32: b31[0..2] b32[3..4] std[5..10] mean[11..16]
#define SMEM_BYTES 149600

__device__ __align__(16) unsigned char g_wbuf[4][WBUF_BYTES];

__device__ __forceinline__ uint32_t smem_u32(const void* p) {
    uint32_t a;
    asm("{ .reg .u64 t; cvta.to.shared.u64 t, %1; cvt.u32.u64 %0, t; }"
        : "=r"(a) : "l"(p));
    return a;
}

__device__ __forceinline__ void ldsm4(uint32_t& r0, uint32_t& r1, uint32_t& r2, uint32_t& r3,
                                      uint32_t addr) {
    asm volatile("ldmatrix.sync.aligned.m8n8.x4.shared.b16 {%0,%1,%2,%3}, [%4];"
                 : "=r"(r0), "=r"(r1), "=r"(r2), "=r"(r3) : "r"(addr));
}

__device__ __forceinline__ void mma_bf16(float& c0, float& c1, float& c2, float& c3,
                                         uint32_t a0, uint32_t a1, uint32_t a2, uint32_t a3,
                                         uint32_t b0, uint32_t b1) {
    asm volatile(
        "mma.sync.aligned.m16n8k16.row.col.f32.bf16.bf16.f32 "
        "{%0,%1,%2,%3}, {%4,%5,%6,%7}, {%8,%9}, {%0,%1,%2,%3};\n"
        : "+f"(c0), "+f"(c1), "+f"(c2), "+f"(c3)
        : "r"(a0), "r"(a1), "r"(a2), "r"(a3), "r"(b0), "r"(b1));
}

__device__ __forceinline__ uint32_t pack_bf2(float lo, float hi) {
    __nv_bfloat162 h = __floats2bfloat162_rn(lo, hi);
    return *reinterpret_cast<uint32_t*>(&h);
}

__device__ __forceinline__ uint32_t tanh2(uint32_t v) {
    asm("tanh.approx.bf16x2 %0, %0;" : "+r"(v));
    return v;
}

// ---------------- prep kernel: fp32 weights -> padded bf16 rows + bias ------
__global__ void prep_weights(const float* __restrict__ w21, const float* __restrict__ b21,
                             const float* __restrict__ wm1, const float* __restrict__ bm1,
                             const float* __restrict__ w22, const float* __restrict__ b22,
                             const float* __restrict__ wm2, const float* __restrict__ bm2) {
    const float* W[4] = {w21, wm1, w22, wm2};
    const float* Bv[4] = {b21, bm1, b22, bm2};
    int m = blockIdx.x;
    unsigned char* dst = g_wbuf[m];
    const float* src = W[m];
    for (int i = threadIdx.x; i < 128 * 68; i += blockDim.x) {
        int r = i / 68, p = i % 68;
        uint32_t val = 0;
        if (p < 64) {
            float2 v = reinterpret_cast<const float2*>(src)[r * 64 + p];
            val = pack_bf2(v.x, v.y);
        }
        reinterpret_cast<uint32_t*>(dst + r * ROWB)[p] = val;
    }
    if (threadIdx.x < 128)
        reinterpret_cast<float*>(dst + 128 * ROWB)[threadIdx.x] = Bv[m][threadIdx.x];
}

// ---------------- cp.async weight staging (one commit group per call) -------
__device__ __forceinline__ void cp_issue(char* sb, int midx, int buf_off, int tid) {
    uint32_t wbase = smem_u32(sb) + buf_off;
    const unsigned char* g = g_wbuf[midx];
    #pragma unroll
    for (int it = 0; it < 5; ++it) {
        int i = tid + it * THREADS;
        if (i < WBUF_BYTES / 16) {
            asm volatile("cp.async.cg.shared.global [%0], [%1], 16;"
                         :: "r"(wbase + i * 16),
                            "l"(__cvta_generic_to_global(g + i * 16)));
        }
    }
    asm volatile("cp.async.commit_group;");
}

template <int N>
__device__ __forceinline__ void cp_wait_sync() {
    asm volatile("cp.async.wait_group %0;" :: "n"(N));
    __syncthreads();
}

// ---------------- one 128x128x128 layer, 4x4 warp tiling --------------------
// warp w: rows [32*(w&3), +32), cols [32*(w>>2), +32). out = tanh(in @ W^T + b).
// Writes OFF_A; in_off may equal OFF_A (internal barrier separates read/write).
__device__ __forceinline__ void gemm_tanh(char* sb, int in_off, int w_off,
                                          int warp, int lane) {
    const int rw = warp & 3, cw = warp >> 2;
    const int g = lane >> 2, tg = lane & 3;
    float acc[2][4][4];
    #pragma unroll
    for (int mt = 0; mt < 2; ++mt)
        #pragma unroll
        for (int t = 0; t < 4; ++t)
            acc[mt][t][0] = acc[mt][t][1] = acc[mt][t][2] = acc[mt][t][3] = 0.f;

    const uint32_t base = smem_u32(sb);
    const int l7 = lane & 7;
    const int rA = (((lane >> 3) & 1) << 3) + l7;
    const int kA = (lane >> 4) << 3;
    uint32_t aaddr0 = base + in_off + (rw * 32 + rA) * ROWB + kA * 2;
    uint32_t aaddr1 = aaddr0 + 16 * ROWB;
    const int rB = (((lane >> 4) & 1) << 3) + l7;
    const int kB = ((lane >> 3) & 1) << 3;
    uint32_t baddr = base + w_off + (cw * 32 + rB) * ROWB + kB * 2;

    #pragma unroll
    for (int kk = 0; kk < 8; ++kk) {
        uint32_t a0, a1, a2, a3, a4, a5, a6, a7;
        ldsm4(a0, a1, a2, a3, aaddr0 + kk * 32);
        ldsm4(a4, a5, a6, a7, aaddr1 + kk * 32);
        #pragma unroll
        for (int np = 0; np < 2; ++np) {
            uint32_t b0, b1, b2, b3;
            ldsm4(b0, b1, b2, b3, baddr + np * (16 * ROWB) + kk * 32);
            mma_bf16(acc[0][2*np][0],   acc[0][2*np][1],   acc[0][2*np][2],   acc[0][2*np][3],
                     a0, a1, a2, a3, b0, b1);
            mma_bf16(acc[0][2*np+1][0], acc[0][2*np+1][1], acc[0][2*np+1][2], acc[0][2*np+1][3],
                     a0, a1, a2, a3, b2, b3);
            mma_bf16(acc[1][2*np][0],   acc[1][2*np][1],   acc[1][2*np][2],   acc[1][2*np][3],
                     a4, a5, a6, a7, b0, b1);
            mma_bf16(acc[1][2*np+1][0], acc[1][2*np+1][1], acc[1][2*np+1][2], acc[1][2*np+1][3],
                     a4, a5, a6, a7, b2, b3);
        }
    }
    __syncthreads();  // all warps' reads of in_off / W complete before stores

    const float* bias = reinterpret_cast<const float*>(sb + w_off + 128 * ROWB);
    #pragma unroll
    for (int mt = 0; mt < 2; ++mt) {
        char* o0 = sb + OFF_A + (rw * 32 + mt * 16 + g) * ROWB + (cw * 32 + tg * 2) * 2;
        #pragma unroll
        for (int t = 0; t < 4; ++t) {
            int c = cw * 32 + t * 8 + tg * 2;
            float b0 = bias[c], b1 = bias[c + 1];
            uint32_t p0 = tanh2(pack_bf2(acc[mt][t][0] + b0, acc[mt][t][1] + b1));
            uint32_t p1 = tanh2(pack_bf2(acc[mt][t][2] + b0, acc[mt][t][3] + b1));
            *reinterpret_cast<uint32_t*>(o0 + t * 16) = p0;
            *reinterpret_cast<uint32_t*>(o0 + 8 * ROWB + t * 16) = p1;
        }
    }
}

__global__ void __launch_bounds__(THREADS, 1)
barriernet_kernel(const float* __restrict__ x,
                  const float* __restrict__ mean_, const float* __restrict__ std_,
                  const float* __restrict__ fc1_w, const float* __restrict__ fc1_b,
                  const float* __restrict__ fc31_w, const float* __restrict__ fc31_b,
                  const float* __restrict__ fc32_w, const float* __restrict__ fc32_b,
                  float* __restrict__ out)
{
    extern __shared__ char sb[];
    const int tid  = threadIdx.x;
    const int warp = tid >> 5;
    const int lane = tid & 31;
    const int row0 = blockIdx.x * ROWS_PER_CTA;

    float* xs   = reinterpret_cast<float*>(sb + OFF_X);
    float* w1s  = reinterpret_cast<float*>(sb + OFF_FC1W);
    float* b1s  = reinterpret_cast<float*>(sb + OFF_FC1B);
    float* w31s = reinterpret_cast<float*>(sb + OFF_W31);
    float* w32s = reinterpret_cast<float*>(sb + OFF_W32);
    float* sml  = reinterpret_cast<float*>(sb + OFF_SML);

    // fc21 weights first: overlaps all constant staging + fc1 compute
    cp_issue(sb, 0, OFF_W0, tid);                         // group: {fc21}

    for (int i = tid; i < 768; i += THREADS) { xs[i] = x[(size_t)row0 * 6 + i]; w1s[i] = fc1_w[i]; }
    for (int i = tid; i < 384; i += THREADS) w31s[i] = fc31_w[i];
    for (int i = tid; i < 256; i += THREADS) w32s[i] = fc32_w[i];
    if (tid < 128) b1s[tid] = fc1_b[tid];
    if (tid < 3)  sml[tid] = fc31_b[tid];
    if (tid >= 3 && tid < 5) sml[tid] = fc32_b[tid - 3];
    if (tid >= 5 && tid < 11) sml[tid] = std_[tid - 5];
    if (tid >= 11 && tid < 17) sml[tid] = mean_[tid - 11];
    __syncthreads();

    // ---- fc1 (K=6) + tanh -> H (bf16), 2 adjacent cols per thread ----
    {
        const int cp2 = tid & 63;                 // column pair index
        const int rbase = tid >> 6;               // 0..7
        const float* wA = &w1s[(2 * cp2) * 6];
        const float* wB = &w1s[(2 * cp2 + 1) * 6];
        float wa0 = wA[0], wa1 = wA[1], wa2 = wA[2], wa3 = wA[3], wa4 = wA[4], wa5 = wA[5];
        float wb0 = wB[0], wb1 = wB[1], wb2 = wB[2], wb3 = wB[3], wb4 = wB[4], wb5 = wB[5];
        float ba = b1s[2 * cp2], bb = b1s[2 * cp2 + 1];
        #pragma unroll
        for (int it = 0; it < 16; ++it) {
            int row = rbase + it * 8;
            const float* xr = &xs[row * 6];
            float x0v = xr[0], x1v = xr[1], x2v = xr[2], x3v = xr[3], x4v = xr[4], x5v = xr[5];
            float sA = ba + x0v*wa0 + x1v*wa1 + x2v*wa2 + x3v*wa3 + x4v*wa4 + x5v*wa5;
            float sB = bb + x0v*wb0 + x1v*wb1 + x2v*wb2 + x3v*wb3 + x4v*wb4 + x5v*wb5;
            *reinterpret_cast<uint32_t*>(sb + OFF_H + row * ROWB + cp2 * 4) =
                tanh2(pack_bf2(sA, sB));
        }
    }
    cp_wait_sync<0>();                                    // fc21 staged; H published

    // ---- path 1: fc21 -> fcm1 ----
    cp_issue(sb, 1, OFF_W1B, tid);                        // fcm1 streams behind fc21 MMA
    gemm_tanh(sb, OFF_H, OFF_W0, warp, lane);
    cp_issue(sb, 2, OFF_W0, tid);                         // fc22 (W0 reads done at internal barrier)
    cp_wait_sync<1>();                                    // fcm1 ready; A published
    gemm_tanh(sb, OFF_A, OFF_W1B, warp, lane);
    cp_issue(sb, 3, OFF_W1B, tid);                        // fcm2
    cp_wait_sync<1>();                                    // fc22 ready; A published

    // ---- fc31 head: row = warp*8 + lane (lane<8), result kept in registers ----
    float d0 = 0.f, d1 = 0.f, d2 = 0.f;
    if (lane < 8) {
        int row = warp * 8 + lane;
        const uint32_t* a = reinterpret_cast<const uint32_t*>(sb + OFF_A + row * ROWB);
        d0 = sml[0]; d1 = sml[1]; d2 = sml[2];
        #pragma unroll 8
        for (int i = 0; i < 64; ++i) {
            uint32_t u = a[i];
            float2 av = __bfloat1622float2(*reinterpret_cast<const __nv_bfloat162*>(&u));
            int k = 2 * i;
            d0 += av.x * w31s[k]       + av.y * w31s[k + 1];
            d1 += av.x * w31s[128 + k] + av.y * w31s[128 + k + 1];
            d2 += av.x * w31s[256 + k] + av.y * w31s[256 + k + 1];
        }
    }
    // gemm fc22 reads H (not A); its internal barrier fences head1 A-reads vs stores
    gemm_tanh(sb, OFF_H, OFF_W0, warp, lane);
    cp_wait_sync<0>();                                    // fcm2 ready; A published
    gemm_tanh(sb, OFF_A, OFF_W1B, warp, lane);
    __syncthreads();

    // ---- fc32 head + HOCBF/QP epilogue ----
    if (lane < 8) {
        int row = warp * 8 + lane;
        const uint32_t* a = reinterpret_cast<const uint32_t*>(sb + OFF_A + row * ROWB);
        float z0 = sml[3], z1 = sml[4];
        #pragma unroll 8
        for (int i = 0; i < 64; ++i) {
            uint32_t u = a[i];
            float2 av = __bfloat1622float2(*reinterpret_cast<const __nv_bfloat162*>(&u));
            int k = 2 * i;
            z0 += av.x * w32s[k]       + av.y * w32s[k + 1];
            z1 += av.x * w32s[128 + k] + av.y * w32s[128 + k + 1];
        }
        float s0 = 4.f / (1.f + expf(-z0));
        float s1 = 4.f / (1.f + expf(-z1));

        const float* xr = &xs[row * 6];
        float px = xr[0] * sml[5] + sml[11];
        float vx = xr[1] * sml[6] + sml[12];
        float py = xr[2] * sml[7] + sml[13];
        float vy = xr[3] * sml[8] + sml[14];
        float pz = xr[4] * sml[9] + sml[15];
        float vz = xr[5] * sml[10] + sml[16];

        float dx = px - 10.f, dy = py - 10.f, dz = pz - 9.f;
        float dx2 = dx*dx, dy2 = dy*dy, dz2 = dz*dz;
        float dx3 = dx2*dx, dy3 = dy2*dy, dz3 = dz2*dz;
        float barrier = dx2*dx2 + dy2*dy2 + dz2*dz2 - 2401.f;  // R^4
        float bdot = 4.f * (dx3*vx + dy3*vy + dz3*vz);
        float Lf2b = 12.f * (dx2*vx*vx + dy2*vy*vy + dz2*vz*vz);
        float Gx = -4.f*dx3, Gy = -4.f*dy3, Gz = -4.f*dz3;
        float hv = Lf2b + (s0 + s1) * bdot + s0 * s1 * barrier;

        float u0 = -d0, u1 = -d1, u2 = -d2;
        float Gu = Gx*u0 + Gy*u1 + Gz*u2;
        float GG = Gx*Gx + Gy*Gy + Gz*Gz;
        float lam = fmaxf(Gu - hv, 0.f) / GG;

        float* o = out + (size_t)(row0 + row) * 3;
        o[0] = u0 - lam * Gx;
        o[1] = u1 - lam * Gy;
        o[2] = u2 - lam * Gz;
    }
}

extern "C" void kernel_launch(void* const* d_in, const int* in_sizes, int n_in,
                              void* d_out, int out_size) {
    const float* x      = (const float*)d_in[0];
    const float* mean_  = (const float*)d_in[1];
    const float* std_   = (const float*)d_in[2];
    const float* fc1_w  = (const float*)d_in[3];
    const float* fc1_b  = (const float*)d_in[4];
    const float* fc21_w = (const float*)d_in[5];
    const float* fc21_b = (const float*)d_in[6];
    const float* fc22_w = (const float*)d_in[7];
    const float* fc22_b = (const float*)d_in[8];
    const float* fcm1_w = (const float*)d_in[9];
    const float* fcm1_b = (const float*)d_in[10];
    const float* fcm2_w = (const float*)d_in[11];
    const float* fcm2_b = (const float*)d_in[12];
    const float* fc31_w = (const float*)d_in[13];
    const float* fc31_b = (const float*)d_in[14];
    const float* fc32_w = (const float*)d_in[15];
    const float* fc32_b = (const float*)d_in[16];
    float* out = (float*)d_out;

    int B = in_sizes[0] / 6;
    int grid = B / ROWS_PER_CTA;

    prep_weights<<<4, 256>>>(fc21_w, fc21_b, fcm1_w, fcm1_b,
                             fc22_w, fc22_b, fcm2_w, fcm2_b);

    cudaFuncSetAttribute(barriernet_kernel,
                         cudaFuncAttributeMaxDynamicSharedMemorySize, SMEM_BYTES);
    barriernet_kernel<<<grid, THREADS, SMEM_BYTES>>>(
        x, mean_, std_, fc1_w, fc1_b, fc31_w, fc31_b, fc32_w, fc32_b, out);
}

// round 7
// speedup vs baseline: 1.2591x; 1.2591x over previous
#include <cuda_runtime.h>
#include <cuda_bf16.h>
#include <cstdint>

// ---------------------------------------------------------------------------
// BarrierNet on GB300, round 7: R6 with cp.async copy-count fix (2176 chunks,
// not 2048 — the missing tail fed NaNs into the MMA).
//   256 thr, 2 CTA/SM, 4x2 warp tiling, bf16 m16n8k16 mma.sync,
//   overlapped weight prefetch, tanh.approx.bf16x2, biases staged once.
// ---------------------------------------------------------------------------

#define THREADS 256
#define ROWS_PER_CTA 128
#define STRB 136            // bf16 elems per smem row -> bank permutation
#define ROWB (STRB * 2)     // 272 bytes per row
#define WMAT_BYTES 34816    // 128*272 weight rows (matrix only)
#define WMAT_CHUNKS (WMAT_BYTES / 16)   // 2176

// byte offsets into dynamic smem
#define OFF_W    0                      // staged weight matrix (34816)
#define OFF_H    34816                  // activations H
#define OFF_A    69632                  // activations A
#define OFF_B4   104448                 // 4 x 128 f32 biases
#define OFF_X    106496                 // 128*6 f32
#define OFF_W31  109568                 // 384 f32
#define OFF_W32  111104                 // 256 f32
#define OFF_SML  112128                 // 17 f32: b31[0..2] b32[3..4] std[5..10] mean[11..16]
#define SMEM_BYTES 112208

__device__ __align__(16) unsigned char g_wmat[4][WMAT_BYTES];
__device__ float g_wbias[4][128];

__device__ __forceinline__ uint32_t smem_u32(const void* p) {
    uint32_t a;
    asm("{ .reg .u64 t; cvta.to.shared.u64 t, %1; cvt.u32.u64 %0, t; }"
        : "=r"(a) : "l"(p));
    return a;
}

__device__ __forceinline__ void ldsm4(uint32_t& r0, uint32_t& r1, uint32_t& r2, uint32_t& r3,
                                      uint32_t addr) {
    asm volatile("ldmatrix.sync.aligned.m8n8.x4.shared.b16 {%0,%1,%2,%3}, [%4];"
                 : "=r"(r0), "=r"(r1), "=r"(r2), "=r"(r3) : "r"(addr));
}

__device__ __forceinline__ void mma_bf16(float& c0, float& c1, float& c2, float& c3,
                                         uint32_t a0, uint32_t a1, uint32_t a2, uint32_t a3,
                                         uint32_t b0, uint32_t b1) {
    asm volatile(
        "mma.sync.aligned.m16n8k16.row.col.f32.bf16.bf16.f32 "
        "{%0,%1,%2,%3}, {%4,%5,%6,%7}, {%8,%9}, {%0,%1,%2,%3};\n"
        : "+f"(c0), "+f"(c1), "+f"(c2), "+f"(c3)
        : "r"(a0), "r"(a1), "r"(a2), "r"(a3), "r"(b0), "r"(b1));
}

__device__ __forceinline__ uint32_t pack_bf2(float lo, float hi) {
    __nv_bfloat162 h = __floats2bfloat162_rn(lo, hi);
    return *reinterpret_cast<uint32_t*>(&h);
}
__device__ __forceinline__ uint32_t tanh2(uint32_t v) {
    asm("tanh.approx.bf16x2 %0, %0;" : "+r"(v));
    return v;
}

// ---------------- prep kernel: fp32 weights -> padded bf16 rows + biases ----
__global__ void prep_weights(const float* __restrict__ w21, const float* __restrict__ b21,
                             const float* __restrict__ wm1, const float* __restrict__ bm1,
                             const float* __restrict__ w22, const float* __restrict__ b22,
                             const float* __restrict__ wm2, const float* __restrict__ bm2) {
    const float* W[4]  = {w21, wm1, w22, wm2};
    const float* Bv[4] = {b21, bm1, b22, bm2};
    int m = blockIdx.x;
    unsigned char* dst = g_wmat[m];
    const float* src = W[m];
    // 128 rows x 68 u32 (64 data pairs + 4 pad pairs)
    for (int i = threadIdx.x; i < 128 * 68; i += blockDim.x) {
        int r = i / 68, p = i % 68;
        uint32_t val = 0;
        if (p < 64) {
            float2 v = reinterpret_cast<const float2*>(src)[r * 64 + p];
            val = pack_bf2(v.x, v.y);
        }
        reinterpret_cast<uint32_t*>(dst + r * ROWB)[p] = val;
    }
    if (threadIdx.x < 128) g_wbias[m][threadIdx.x] = Bv[m][threadIdx.x];
}

// ---------------- cp.async weight staging (2176 x 16B) ----------------------
__device__ __forceinline__ void cp_issue(char* sb, int midx, int tid) {
    uint32_t wbase = smem_u32(sb) + OFF_W;
    const unsigned char* g = g_wmat[midx];
    #pragma unroll
    for (int it = 0; it < 9; ++it) {
        int i = tid + it * THREADS;
        if (i < WMAT_CHUNKS) {
            asm volatile("cp.async.cg.shared.global [%0], [%1], 16;"
                         :: "r"(wbase + i * 16),
                            "l"(__cvta_generic_to_global(g + i * 16)));
        }
    }
    asm volatile("cp.async.commit_group;");
}

__device__ __forceinline__ void cp_wait_sync() {
    asm volatile("cp.async.wait_group 0;");
    __syncthreads();
}

// ---------------- one 128x128x128 layer, 4x2 warp tiling --------------------
// warp w: rows [32*(w&3), +32), cols [64*(w>>2), +64). out = tanh(in @ W^T + b).
// Writes OFF_A; in_off may equal OFF_A (internal barrier separates read/write).
// After the internal barrier (all W/A MMA reads done) issues cp.async for the
// next layer's weights (next_midx >= 0), overlapping the load with the epilogue.
__device__ __forceinline__ void gemm_tanh(char* sb, int in_off, const float* __restrict__ bias,
                                          int next_midx, int warp, int lane, int tid) {
    const int rw = warp & 3, cw = warp >> 2;
    const int g = lane >> 2, tg = lane & 3;
    float acc[2][8][4];
    #pragma unroll
    for (int mt = 0; mt < 2; ++mt)
        #pragma unroll
        for (int t = 0; t < 8; ++t)
            acc[mt][t][0] = acc[mt][t][1] = acc[mt][t][2] = acc[mt][t][3] = 0.f;

    const uint32_t base = smem_u32(sb);
    const int l7 = lane & 7;
    const int rA = (((lane >> 3) & 1) << 3) + l7;
    const int kA = (lane >> 4) << 3;
    uint32_t aaddr0 = base + in_off + (rw * 32 + rA) * ROWB + kA * 2;
    uint32_t aaddr1 = aaddr0 + 16 * ROWB;
    const int rB = (((lane >> 4) & 1) << 3) + l7;
    const int kB = ((lane >> 3) & 1) << 3;
    uint32_t baddr = base + OFF_W + (cw * 64 + rB) * ROWB + kB * 2;

    #pragma unroll
    for (int kk = 0; kk < 8; ++kk) {
        uint32_t a0, a1, a2, a3, a4, a5, a6, a7;
        ldsm4(a0, a1, a2, a3, aaddr0 + kk * 32);
        ldsm4(a4, a5, a6, a7, aaddr1 + kk * 32);
        #pragma unroll
        for (int np = 0; np < 4; ++np) {
            uint32_t b0, b1, b2, b3;
            ldsm4(b0, b1, b2, b3, baddr + np * (16 * ROWB) + kk * 32);
            mma_bf16(acc[0][2*np][0],   acc[0][2*np][1],   acc[0][2*np][2],   acc[0][2*np][3],
                     a0, a1, a2, a3, b0, b1);
            mma_bf16(acc[0][2*np+1][0], acc[0][2*np+1][1], acc[0][2*np+1][2], acc[0][2*np+1][3],
                     a0, a1, a2, a3, b2, b3);
            mma_bf16(acc[1][2*np][0],   acc[1][2*np][1],   acc[1][2*np][2],   acc[1][2*np][3],
                     a4, a5, a6, a7, b0, b1);
            mma_bf16(acc[1][2*np+1][0], acc[1][2*np+1][1], acc[1][2*np+1][2], acc[1][2*np+1][3],
                     a4, a5, a6, a7, b2, b3);
        }
    }
    __syncthreads();  // all warps' MMA reads of in_off / W complete

    if (next_midx >= 0) cp_issue(sb, next_midx, tid);  // W region free -> prefetch

    #pragma unroll
    for (int mt = 0; mt < 2; ++mt) {
        char* o0 = sb + OFF_A + (rw * 32 + mt * 16 + g) * ROWB + cw * 128;
        #pragma unroll
        for (int t = 0; t < 8; ++t) {
            int c = cw * 64 + t * 8 + tg * 2;
            float b0 = bias[c], b1 = bias[c + 1];
            uint32_t p0 = tanh2(pack_bf2(acc[mt][t][0] + b0, acc[mt][t][1] + b1));
            uint32_t p1 = tanh2(pack_bf2(acc[mt][t][2] + b0, acc[mt][t][3] + b1));
            *reinterpret_cast<uint32_t*>(o0 + (t * 8 + tg * 2) * 2) = p0;
            *reinterpret_cast<uint32_t*>(o0 + 8 * ROWB + (t * 8 + tg * 2) * 2) = p1;
        }
    }
}

__global__ void __launch_bounds__(THREADS, 2)
barriernet_kernel(const float* __restrict__ x,
                  const float* __restrict__ mean_, const float* __restrict__ std_,
                  const float* __restrict__ fc1_w, const float* __restrict__ fc1_b,
                  const float* __restrict__ fc31_w, const float* __restrict__ fc31_b,
                  const float* __restrict__ fc32_w, const float* __restrict__ fc32_b,
                  float* __restrict__ out)
{
    extern __shared__ char sb[];
    const int tid  = threadIdx.x;
    const int warp = tid >> 5;
    const int lane = tid & 31;
    const int row0 = blockIdx.x * ROWS_PER_CTA;

    cp_issue(sb, 0, tid);   // fc21 weights stream behind staging + fc1

    float* xs   = reinterpret_cast<float*>(sb + OFF_X);
    float* b4   = reinterpret_cast<float*>(sb + OFF_B4);
    float* w31s = reinterpret_cast<float*>(sb + OFF_W31);
    float* w32s = reinterpret_cast<float*>(sb + OFF_W32);
    float* sml  = reinterpret_cast<float*>(sb + OFF_SML);

    for (int i = tid; i < 768; i += THREADS) xs[i] = x[(size_t)row0 * 6 + i];
    for (int i = tid; i < 512; i += THREADS) b4[i] = g_wbias[i >> 7][i & 127];
    for (int i = tid; i < 384; i += THREADS) w31s[i] = fc31_w[i];
    if (tid < 256) w32s[tid] = fc32_w[tid];
    if (tid < 3)  sml[tid] = fc31_b[tid];
    if (tid >= 3 && tid < 5) sml[tid] = fc32_b[tid - 3];
    if (tid >= 5 && tid < 11) sml[tid] = std_[tid - 5];
    if (tid >= 11 && tid < 17) sml[tid] = mean_[tid - 11];
    __syncthreads();

    // ---- fc1 (K=6) + tanh2 -> H (bf16); weights per-thread from global ----
    {
        const int cp2 = tid & 63;          // column pair
        const int rh  = tid >> 6;          // row quarter 0..3
        const int c0 = 2 * cp2;
        const float* wA = fc1_w + c0 * 6;
        const float* wB = wA + 6;
        float wa0 = wA[0], wa1 = wA[1], wa2 = wA[2], wa3 = wA[3], wa4 = wA[4], wa5 = wA[5];
        float wb0 = wB[0], wb1 = wB[1], wb2 = wB[2], wb3 = wB[3], wb4 = wB[4], wb5 = wB[5];
        float ba = fc1_b[c0], bb = fc1_b[c0 + 1];
        #pragma unroll 8
        for (int rr = 0; rr < 32; ++rr) {
            int row = rh * 32 + rr;
            const float* xr = &xs[row * 6];
            float x0v = xr[0], x1v = xr[1], x2v = xr[2], x3v = xr[3], x4v = xr[4], x5v = xr[5];
            float sA = ba + x0v*wa0 + x1v*wa1 + x2v*wa2 + x3v*wa3 + x4v*wa4 + x5v*wa5;
            float sB = bb + x0v*wb0 + x1v*wb1 + x2v*wb2 + x3v*wb3 + x4v*wb4 + x5v*wb5;
            *reinterpret_cast<uint32_t*>(sb + OFF_H + row * ROWB + cp2 * 4) =
                tanh2(pack_bf2(sA, sB));
        }
    }
    cp_wait_sync();         // fc21 staged; H published

    // ---- path 1: fc21 -> fcm1 ----
    gemm_tanh(sb, OFF_H, b4 + 0 * 128, 1, warp, lane, tid);   // prefetch fcm1
    cp_wait_sync();                                           // fcm1 ready; A published
    gemm_tanh(sb, OFF_A, b4 + 1 * 128, 2, warp, lane, tid);   // prefetch fc22
    cp_wait_sync();                                           // fc22 ready; A published

    // ---- fc31 head (reads A, kept in registers) ----
    float d0 = 0.f, d1 = 0.f, d2 = 0.f;
    if (lane < 16) {
        int row = warp * 16 + lane;
        const uint32_t* a = reinterpret_cast<const uint32_t*>(sb + OFF_A + row * ROWB);
        d0 = sml[0]; d1 = sml[1]; d2 = sml[2];
        #pragma unroll 8
        for (int i = 0; i < 64; ++i) {
            uint32_t u = a[i];
            float2 av = __bfloat1622float2(*reinterpret_cast<const __nv_bfloat162*>(&u));
            int k = 2 * i;
            d0 += av.x * w31s[k]       + av.y * w31s[k + 1];
            d1 += av.x * w31s[128 + k] + av.y * w31s[128 + k + 1];
            d2 += av.x * w31s[256 + k] + av.y * w31s[256 + k + 1];
        }
    }

    // ---- path 2: fc22 -> fcm2 ----
    // fc22 gemm reads H; its internal barrier fences head1 A-reads vs A-stores.
    gemm_tanh(sb, OFF_H, b4 + 2 * 128, 3, warp, lane, tid);   // prefetch fcm2
    cp_wait_sync();                                           // fcm2 ready; A published
    gemm_tanh(sb, OFF_A, b4 + 3 * 128, -1, warp, lane, tid);
    __syncthreads();                                          // publish final A

    // ---- fc32 head + HOCBF/QP epilogue ----
    if (lane < 16) {
        int row = warp * 16 + lane;
        const uint32_t* a = reinterpret_cast<const uint32_t*>(sb + OFF_A + row * ROWB);
        float z0 = sml[3], z1 = sml[4];
        #pragma unroll 8
        for (int i = 0; i < 64; ++i) {
            uint32_t u = a[i];
            float2 av = __bfloat1622float2(*reinterpret_cast<const __nv_bfloat162*>(&u));
            int k = 2 * i;
            z0 += av.x * w32s[k]       + av.y * w32s[k + 1];
            z1 += av.x * w32s[128 + k] + av.y * w32s[128 + k + 1];
        }
        float s0 = 4.f / (1.f + expf(-z0));
        float s1 = 4.f / (1.f + expf(-z1));

        const float* xr = &xs[row * 6];
        float px = xr[0] * sml[5]  + sml[11];
        float vx = xr[1] * sml[6]  + sml[12];
        float py = xr[2] * sml[7]  + sml[13];
        float vy = xr[3] * sml[8]  + sml[14];
        float pz = xr[4] * sml[9]  + sml[15];
        float vz = xr[5] * sml[10] + sml[16];

        float dx = px - 10.f, dy = py - 10.f, dz = pz - 9.f;
        float dx2 = dx*dx, dy2 = dy*dy, dz2 = dz*dz;
        float dx3 = dx2*dx, dy3 = dy2*dy, dz3 = dz2*dz;
        float barrier = dx2*dx2 + dy2*dy2 + dz2*dz2 - 2401.f;   // R^4 = 7^4
        float bdot = 4.f * (dx3*vx + dy3*vy + dz3*vz);
        float Lf2b = 12.f * (dx2*vx*vx + dy2*vy*vy + dz2*vz*vz);
        float Gx = -4.f*dx3, Gy = -4.f*dy3, Gz = -4.f*dz3;
        float hv = Lf2b + (s0 + s1) * bdot + s0 * s1 * barrier;

        float u0 = -d0, u1 = -d1, u2 = -d2;
        float Gu = Gx*u0 + Gy*u1 + Gz*u2;
        float GG = Gx*Gx + Gy*Gy + Gz*Gz;
        float lam = fmaxf(Gu - hv, 0.f) / GG;

        float* o = out + (size_t)(row0 + row) * 3;
        o[0] = u0 - lam * Gx;
        o[1] = u1 - lam * Gy;
        o[2] = u2 - lam * Gz;
    }
}

extern "C" void kernel_launch(void* const* d_in, const int* in_sizes, int n_in,
                              void* d_out, int out_size) {
    const float* x      = (const float*)d_in[0];
    const float* mean_  = (const float*)d_in[1];
    const float* std_   = (const float*)d_in[2];
    const float* fc1_w  = (const float*)d_in[3];
    const float* fc1_b  = (const float*)d_in[4];
    const float* fc21_w = (const float*)d_in[5];
    const float* fc21_b = (const float*)d_in[6];
    const float* fc22_w = (const float*)d_in[7];
    const float* fc22_b = (const float*)d_in[8];
    const float* fcm1_w = (const float*)d_in[9];
    const float* fcm1_b = (const float*)d_in[10];
    const float* fcm2_w = (const float*)d_in[11];
    const float* fcm2_b = (const float*)d_in[12];
    const float* fc31_w = (const float*)d_in[13];
    const float* fc31_b = (const float*)d_in[14];
    const float* fc32_w = (const float*)d_in[15];
    const float* fc32_b = (const float*)d_in[16];
    float* out = (float*)d_out;

    int B = in_sizes[0] / 6;
    int grid = B / ROWS_PER_CTA;

    prep_weights<<<4, 256>>>(fc21_w, fc21_b, fcm1_w, fcm1_b,
                             fc22_w, fc22_b, fcm2_w, fcm2_b);

    cudaFuncSetAttribute(barriernet_kernel,
                         cudaFuncAttributeMaxDynamicSharedMemorySize, SMEM_BYTES);
    barriernet_kernel<<<grid, THREADS, SMEM_BYTES>>>(
        x, mean_, std_, fc1_w, fc1_b, fc31_w, fc31_b, fc32_w, fc32_b, out);
}

// round 8
// speedup vs baseline: 1.3122x; 1.0421x over previous
#include <cuda_runtime.h>
#include <cuda_bf16.h>
#include <cstdint>

// ---------------------------------------------------------------------------
// BarrierNet on GB300, round 8: R3 gemm (256 thr, 2 CTA/SM, 4x2 warp tiling,
// bf16 m16n8k16 mma.sync, tanh.approx.f32 epilogue) + TRUE double-buffered
// weight staging: pre-packed bf16 blobs cp.async'd one full gemm ahead.
// H buffer eliminated (fc1 recomputed for path 2) to fit W0+W1+ACT in smem.
// ---------------------------------------------------------------------------

#define THREADS 256
#define ROWS_PER_CTA 128
#define STRB 136            // bf16 elems per smem row -> bank permutation
#define ROWB (STRB * 2)     // 272 bytes per row
#define WMAT_BYTES 34816    // 128*272
#define WMAT_CHUNKS (WMAT_BYTES / 16)   // 2176

// byte offsets into dynamic smem
#define OFF_W0   0
#define OFF_W1   34816
#define OFF_ACT  69632                  // single activation buffer (in-place)
#define OFF_B4   104448                 // 4 x 128 f32 biases
#define OFF_X    106496                 // 128*6 f32
#define OFF_W31  109568                 // 384 f32
#define OFF_W32  111104                 // 256 f32
#define OFF_SML  112128                 // 17 f32: b31[0..2] b32[3..4] std[5..10] mean[11..16]
#define SMEM_BYTES 112208

__device__ __align__(16) unsigned char g_wmat[4][WMAT_BYTES];
__device__ float g_wbias[4][128];

__device__ __forceinline__ uint32_t smem_u32(const void* p) {
    uint32_t a;
    asm("{ .reg .u64 t; cvta.to.shared.u64 t, %1; cvt.u32.u64 %0, t; }"
        : "=r"(a) : "l"(p));
    return a;
}

__device__ __forceinline__ void ldsm4(uint32_t& r0, uint32_t& r1, uint32_t& r2, uint32_t& r3,
                                      uint32_t addr) {
    asm volatile("ldmatrix.sync.aligned.m8n8.x4.shared.b16 {%0,%1,%2,%3}, [%4];"
                 : "=r"(r0), "=r"(r1), "=r"(r2), "=r"(r3) : "r"(addr));
}

__device__ __forceinline__ void mma_bf16(float& c0, float& c1, float& c2, float& c3,
                                         uint32_t a0, uint32_t a1, uint32_t a2, uint32_t a3,
                                         uint32_t b0, uint32_t b1) {
    asm volatile(
        "mma.sync.aligned.m16n8k16.row.col.f32.bf16.bf16.f32 "
        "{%0,%1,%2,%3}, {%4,%5,%6,%7}, {%8,%9}, {%0,%1,%2,%3};\n"
        : "+f"(c0), "+f"(c1), "+f"(c2), "+f"(c3)
        : "r"(a0), "r"(a1), "r"(a2), "r"(a3), "r"(b0), "r"(b1));
}

__device__ __forceinline__ uint32_t pack_bf2(float lo, float hi) {
    __nv_bfloat162 h = __floats2bfloat162_rn(lo, hi);
    return *reinterpret_cast<uint32_t*>(&h);
}
__device__ __forceinline__ float tanh_fast(float x) {
    asm("tanh.approx.f32 %0, %0;" : "+f"(x));
    return x;
}

// ---------------- prep kernel: fp32 weights -> padded bf16 rows + biases ----
__global__ void prep_weights(const float* __restrict__ w21, const float* __restrict__ b21,
                             const float* __restrict__ wm1, const float* __restrict__ bm1,
                             const float* __restrict__ w22, const float* __restrict__ b22,
                             const float* __restrict__ wm2, const float* __restrict__ bm2) {
    const float* W[4]  = {w21, wm1, w22, wm2};
    const float* Bv[4] = {b21, bm1, b22, bm2};
    int m = blockIdx.x;
    unsigned char* dst = g_wmat[m];
    const float* src = W[m];
    for (int i = threadIdx.x; i < 128 * 68; i += blockDim.x) {
        int r = i / 68, p = i % 68;
        uint32_t val = 0;
        if (p < 64) {
            float2 v = reinterpret_cast<const float2*>(src)[r * 64 + p];
            val = pack_bf2(v.x, v.y);
        }
        reinterpret_cast<uint32_t*>(dst + r * ROWB)[p] = val;
    }
    if (threadIdx.x < 128) g_wbias[m][threadIdx.x] = Bv[m][threadIdx.x];
}

// ---------------- cp.async weight staging (2176 x 16B, one commit group) ----
__device__ __forceinline__ void cp_issue(char* sb, int midx, uint32_t w_off, int tid) {
    uint32_t wbase = smem_u32(sb) + w_off;
    const unsigned char* g = g_wmat[midx];
    #pragma unroll
    for (int it = 0; it < 9; ++it) {
        int i = tid + it * THREADS;
        if (i < WMAT_CHUNKS) {
            asm volatile("cp.async.cg.shared.global [%0], [%1], 16;"
                         :: "r"(wbase + i * 16),
                            "l"(__cvta_generic_to_global(g + i * 16)));
        }
    }
    asm volatile("cp.async.commit_group;");
}

template <int N>
__device__ __forceinline__ void cp_wait_sync() {
    asm volatile("cp.async.wait_group %0;" :: "n"(N));
    __syncthreads();
}

// ---------------- fc1 (K=6) + tanh -> ACT (bf16), weights from global -------
__device__ __forceinline__ void fc1_to_act(char* sb, const float* __restrict__ fc1_w,
                                           const float* __restrict__ fc1_b,
                                           const float* __restrict__ xs, int tid) {
    const int cp2 = tid & 63;          // column pair
    const int rh  = tid >> 6;          // row quarter 0..3
    const int c0 = 2 * cp2;
    const float* wA = fc1_w + c0 * 6;
    const float* wB = wA + 6;
    float wa0 = wA[0], wa1 = wA[1], wa2 = wA[2], wa3 = wA[3], wa4 = wA[4], wa5 = wA[5];
    float wb0 = wB[0], wb1 = wB[1], wb2 = wB[2], wb3 = wB[3], wb4 = wB[4], wb5 = wB[5];
    float ba = fc1_b[c0], bb = fc1_b[c0 + 1];
    #pragma unroll 8
    for (int rr = 0; rr < 32; ++rr) {
        int row = rh * 32 + rr;
        const float* xr = &xs[row * 6];
        float x0v = xr[0], x1v = xr[1], x2v = xr[2], x3v = xr[3], x4v = xr[4], x5v = xr[5];
        float sA = ba + x0v*wa0 + x1v*wa1 + x2v*wa2 + x3v*wa3 + x4v*wa4 + x5v*wa5;
        float sB = bb + x0v*wb0 + x1v*wb1 + x2v*wb2 + x3v*wb3 + x4v*wb4 + x5v*wb5;
        *reinterpret_cast<uint32_t*>(sb + OFF_ACT + row * ROWB + cp2 * 4) =
            pack_bf2(tanh_fast(sA), tanh_fast(sB));
    }
}

// ---------------- one 128x128x128 layer, 4x2 warp tiling, in-place ACT ------
// warp w: rows [32*(w&3), +32), cols [64*(w>>2), +64). ACT = tanh(ACT @ W^T + b).
// After the internal barrier (all MMA reads done) optionally issues cp.async
// for a future layer's weights into next_woff.
__device__ __forceinline__ void gemm_tanh(char* sb, uint32_t w_off,
                                          const float* __restrict__ bias,
                                          int next_midx, uint32_t next_woff,
                                          int warp, int lane, int tid) {
    const int rw = warp & 3, cw = warp >> 2;
    const int g = lane >> 2, tg = lane & 3;
    float acc[2][8][4];
    #pragma unroll
    for (int mt = 0; mt < 2; ++mt)
        #pragma unroll
        for (int t = 0; t < 8; ++t)
            acc[mt][t][0] = acc[mt][t][1] = acc[mt][t][2] = acc[mt][t][3] = 0.f;

    const uint32_t base = smem_u32(sb);
    const int l7 = lane & 7;
    const int rA = (((lane >> 3) & 1) << 3) + l7;
    const int kA = (lane >> 4) << 3;
    uint32_t aaddr0 = base + OFF_ACT + (rw * 32 + rA) * ROWB + kA * 2;
    uint32_t aaddr1 = aaddr0 + 16 * ROWB;
    const int rB = (((lane >> 4) & 1) << 3) + l7;
    const int kB = ((lane >> 3) & 1) << 3;
    uint32_t baddr = base + w_off + (cw * 64 + rB) * ROWB + kB * 2;

    #pragma unroll
    for (int kk = 0; kk < 8; ++kk) {
        uint32_t a0, a1, a2, a3, a4, a5, a6, a7;
        ldsm4(a0, a1, a2, a3, aaddr0 + kk * 32);
        ldsm4(a4, a5, a6, a7, aaddr1 + kk * 32);
        #pragma unroll
        for (int np = 0; np < 4; ++np) {
            uint32_t b0, b1, b2, b3;
            ldsm4(b0, b1, b2, b3, baddr + np * (16 * ROWB) + kk * 32);
            mma_bf16(acc[0][2*np][0],   acc[0][2*np][1],   acc[0][2*np][2],   acc[0][2*np][3],
                     a0, a1, a2, a3, b0, b1);
            mma_bf16(acc[0][2*np+1][0], acc[0][2*np+1][1], acc[0][2*np+1][2], acc[0][2*np+1][3],
                     a0, a1, a2, a3, b2, b3);
            mma_bf16(acc[1][2*np][0],   acc[1][2*np][1],   acc[1][2*np][2],   acc[1][2*np][3],
                     a4, a5, a6, a7, b0, b1);
            mma_bf16(acc[1][2*np+1][0], acc[1][2*np+1][1], acc[1][2*np+1][2], acc[1][2*np+1][3],
                     a4, a5, a6, a7, b2, b3);
        }
    }
    __syncthreads();  // all warps' MMA reads of ACT / W complete

    if (next_midx >= 0) cp_issue(sb, next_midx, next_woff, tid);

    #pragma unroll
    for (int mt = 0; mt < 2; ++mt) {
        char* o0 = sb + OFF_ACT + (rw * 32 + mt * 16 + g) * ROWB + cw * 128;
        #pragma unroll
        for (int t = 0; t < 8; ++t) {
            int c = cw * 64 + t * 8 + tg * 2;
            float b0 = bias[c], b1 = bias[c + 1];
            uint32_t p0 = pack_bf2(tanh_fast(acc[mt][t][0] + b0), tanh_fast(acc[mt][t][1] + b1));
            uint32_t p1 = pack_bf2(tanh_fast(acc[mt][t][2] + b0), tanh_fast(acc[mt][t][3] + b1));
            *reinterpret_cast<uint32_t*>(o0 + (t * 8 + tg * 2) * 2) = p0;
            *reinterpret_cast<uint32_t*>(o0 + 8 * ROWB + (t * 8 + tg * 2) * 2) = p1;
        }
    }
}

__global__ void __launch_bounds__(THREADS, 2)
barriernet_kernel(const float* __restrict__ x,
                  const float* __restrict__ mean_, const float* __restrict__ std_,
                  const float* __restrict__ fc1_w, const float* __restrict__ fc1_b,
                  const float* __restrict__ fc31_w, const float* __restrict__ fc31_b,
                  const float* __restrict__ fc32_w, const float* __restrict__ fc32_b,
                  float* __restrict__ out)
{
    extern __shared__ char sb[];
    const int tid  = threadIdx.x;
    const int warp = tid >> 5;
    const int lane = tid & 31;
    const int row0 = blockIdx.x * ROWS_PER_CTA;

    cp_issue(sb, 0, OFF_W0, tid);   // G0: fc21 -> W0
    cp_issue(sb, 1, OFF_W1, tid);   // G1: fcm1 -> W1

    float* xs   = reinterpret_cast<float*>(sb + OFF_X);
    float* b4   = reinterpret_cast<float*>(sb + OFF_B4);
    float* w31s = reinterpret_cast<float*>(sb + OFF_W31);
    float* w32s = reinterpret_cast<float*>(sb + OFF_W32);
    float* sml  = reinterpret_cast<float*>(sb + OFF_SML);

    for (int i = tid; i < 768; i += THREADS) xs[i] = x[(size_t)row0 * 6 + i];
    for (int i = tid; i < 512; i += THREADS) b4[i] = g_wbias[i >> 7][i & 127];
    for (int i = tid; i < 384; i += THREADS) w31s[i] = fc31_w[i];
    if (tid < 256) w32s[tid] = fc32_w[tid];
    if (tid < 3)  sml[tid] = fc31_b[tid];
    if (tid >= 3 && tid < 5) sml[tid] = fc32_b[tid - 3];
    if (tid >= 5 && tid < 11) sml[tid] = std_[tid - 5];
    if (tid >= 11 && tid < 17) sml[tid] = mean_[tid - 11];
    __syncthreads();                // xs published for fc1

    fc1_to_act(sb, fc1_w, fc1_b, xs, tid);
    cp_wait_sync<1>();              // G0 (fc21) done; ACT published

    // ---- path 1: fc21 -> fcm1 ----
    gemm_tanh(sb, OFF_W0, b4 + 0 * 128, 2, OFF_W0, warp, lane, tid);  // G2: fc22 -> W0
    cp_wait_sync<1>();              // G1 (fcm1) done; ACT published
    gemm_tanh(sb, OFF_W1, b4 + 1 * 128, 3, OFF_W1, warp, lane, tid);  // G3: fcm2 -> W1
    cp_wait_sync<1>();              // G2 (fc22) done; ACT published

    // ---- fc31 head (reads final path-1 ACT, kept in registers) ----
    float d0 = 0.f, d1 = 0.f, d2 = 0.f;
    if (lane < 16) {
        int row = warp * 16 + lane;
        const uint32_t* a = reinterpret_cast<const uint32_t*>(sb + OFF_ACT + row * ROWB);
        d0 = sml[0]; d1 = sml[1]; d2 = sml[2];
        #pragma unroll 8
        for (int i = 0; i < 64; ++i) {
            uint32_t u = a[i];
            float2 av = __bfloat1622float2(*reinterpret_cast<const __nv_bfloat162*>(&u));
            int k = 2 * i;
            d0 += av.x * w31s[k]       + av.y * w31s[k + 1];
            d1 += av.x * w31s[128 + k] + av.y * w31s[128 + k + 1];
            d2 += av.x * w31s[256 + k] + av.y * w31s[256 + k + 1];
        }
    }
    __syncthreads();                // head reads done before ACT overwrite

    // ---- path 2: fc1 recompute -> fc22 -> fcm2 ----
    fc1_to_act(sb, fc1_w, fc1_b, xs, tid);
    __syncthreads();                // ACT published
    gemm_tanh(sb, OFF_W0, b4 + 2 * 128, -1, 0, warp, lane, tid);
    cp_wait_sync<0>();              // G3 (fcm2) done; ACT published
    gemm_tanh(sb, OFF_W1, b4 + 3 * 128, -1, 0, warp, lane, tid);
    __syncthreads();                // publish final ACT

    // ---- fc32 head + HOCBF/QP epilogue ----
    if (lane < 16) {
        int row = warp * 16 + lane;
        const uint32_t* a = reinterpret_cast<const uint32_t*>(sb + OFF_ACT + row * ROWB);
        float z0 = sml[3], z1 = sml[4];
        #pragma unroll 8
        for (int i = 0; i < 64; ++i) {
            uint32_t u = a[i];
            float2 av = __bfloat1622float2(*reinterpret_cast<const __nv_bfloat162*>(&u));
            int k = 2 * i;
            z0 += av.x * w32s[k]       + av.y * w32s[k + 1];
            z1 += av.x * w32s[128 + k] + av.y * w32s[128 + k + 1];
        }
        float s0 = 4.f / (1.f + expf(-z0));
        float s1 = 4.f / (1.f + expf(-z1));

        const float* xr = &xs[row * 6];
        float px = xr[0] * sml[5]  + sml[11];
        float vx = xr[1] * sml[6]  + sml[12];
        float py = xr[2] * sml[7]  + sml[13];
        float vy = xr[3] * sml[8]  + sml[14];
        float pz = xr[4] * sml[9]  + sml[15];
        float vz = xr[5] * sml[10] + sml[16];

        float dx = px - 10.f, dy = py - 10.f, dz = pz - 9.f;
        float dx2 = dx*dx, dy2 = dy*dy, dz2 = dz*dz;
        float dx3 = dx2*dx, dy3 = dy2*dy, dz3 = dz2*dz;
        float barrier = dx2*dx2 + dy2*dy2 + dz2*dz2 - 2401.f;   // R^4 = 7^4
        float bdot = 4.f * (dx3*vx + dy3*vy + dz3*vz);
        float Lf2b = 12.f * (dx2*vx*vx + dy2*vy*vy + dz2*vz*vz);
        float Gx = -4.f*dx3, Gy = -4.f*dy3, Gz = -4.f*dz3;
        float hv = Lf2b + (s0 + s1) * bdot + s0 * s1 * barrier;

        float u0 = -d0, u1 = -d1, u2 = -d2;
        float Gu = Gx*u0 + Gy*u1 + Gz*u2;
        float GG = Gx*Gx + Gy*Gy + Gz*Gz;
        float lam = fmaxf(Gu - hv, 0.f) / GG;

        float* o = out + (size_t)(row0 + row) * 3;
        o[0] = u0 - lam * Gx;
        o[1] = u1 - lam * Gy;
        o[2] = u2 - lam * Gz;
    }
}

extern "C" void kernel_launch(void* const* d_in, const int* in_sizes, int n_in,
                              void* d_out, int out_size) {
    const float* x      = (const float*)d_in[0];
    const float* mean_  = (const float*)d_in[1];
    const float* std_   = (const float*)d_in[2];
    const float* fc1_w  = (const float*)d_in[3];
    const float* fc1_b  = (const float*)d_in[4];
    const float* fc21_w = (const float*)d_in[5];
    const float* fc21_b = (const float*)d_in[6];
    const float* fc22_w = (const float*)d_in[7];
    const float* fc22_b = (const float*)d_in[8];
    const float* fcm1_w = (const float*)d_in[9];
    const float* fcm1_b = (const float*)d_in[10];
    const float* fcm2_w = (const float*)d_in[11];
    const float* fcm2_b = (const float*)d_in[12];
    const float* fc31_w = (const float*)d_in[13];
    const float* fc31_b = (const float*)d_in[14];
    const float* fc32_w = (const float*)d_in[15];
    const float* fc32_b = (const float*)d_in[16];
    float* out = (float*)d_out;

    int B = in_sizes[0] / 6;
    int grid = B / ROWS_PER_CTA;

    prep_weights<<<4, 256>>>(fc21_w, fc21_b, fcm1_w, fcm1_b,
                             fc22_w, fc22_b, fcm2_w, fcm2_b);

    cudaFuncSetAttribute(barriernet_kernel,
                         cudaFuncAttributeMaxDynamicSharedMemorySize, SMEM_BYTES);
    barriernet_kernel<<<grid, THREADS, SMEM_BYTES>>>(
        x, mean_, std_, fc1_w, fc1_b, fc31_w, fc31_b, fc32_w, fc32_b, out);
}